// round 14
// baseline (speedup 1.0000x reference)
#include <cuda_runtime.h>
#include <cuda_fp16.h>
#include <cstdint>

// Problem constants (fixed by the dataset)
#define H 128
#define TT 4095          // (8192-3)/2 + 1
#define NC 128           // scan chunks
#define LC 32            // chunk length (last chunk = 31)
#define NELEM (H * H)    // 16384 state elements
#define ZSH 136          // padded Zs row stride in halves (conflict-free)
#define CPC 4            // chunks per persistent CTA
#define XRS 1072         // Xr buffer floats (67 rows x 16)

// Scratch (allocation-free rule: __device__ globals)
static __device__ float g_Y[TT * 3 * H];   // Y[t][w][d] = (w_q @ X_t)[w,d]
static __device__ float g_S[NC * NELEM];   // chunk-local end states
static __device__ float g_cin[NC * NELEM]; // carry-in per chunk

static __device__ __forceinline__ uint32_t smem_u32(const void* p) {
    uint32_t a;
    asm("{ .reg .u64 t; cvta.to.shared.u64 t, %1; cvt.u32.u64 %0, t; }"
        : "=r"(a) : "l"(p));
    return a;
}

// ---------------------------------------------------------------------------
// Kernel 1: Y[t][w][:] = sum_v wq[w][v]*x[2t+v][:], os[t][:] = sum_w D[w]*x[2t+w][:]
// ---------------------------------------------------------------------------
__global__ void prep_kernel(const float* __restrict__ in,
                            const float* __restrict__ wq,
                            const float* __restrict__ Dv,
                            float* __restrict__ os_out) {
    int t = blockIdx.x;
    int d = threadIdx.x;
    float x0 = in[(2 * t + 0) * H + d];
    float x1 = in[(2 * t + 1) * H + d];
    float x2 = in[(2 * t + 2) * H + d];
    g_Y[(t * 3 + 0) * H + d] = wq[0] * x0 + wq[1] * x1 + wq[2] * x2;
    g_Y[(t * 3 + 1) * H + d] = wq[3] * x0 + wq[4] * x1 + wq[5] * x2;
    g_Y[(t * 3 + 2) * H + d] = wq[6] * x0 + wq[7] * x1 + wq[8] * x2;
    os_out[t * H + d] = Dv[0] * x0 + Dv[1] * x1 + Dv[2] * x2;
}

// ---------------------------------------------------------------------------
// Kernel 2: chunk-local scan (zero init), double-buffered Y prefetch,
// Xt triplet layout.   [R12 proven]
// ---------------------------------------------------------------------------
__global__ __launch_bounds__(256) void scan0_kernel(const float* __restrict__ in,
                                                    const float* __restrict__ Lam) {
    __shared__ float Ys[2][8 * 384];
    __shared__ float Xt[LC * 16 * 4];

    int c   = blockIdx.y;
    int a0  = blockIdx.x * 16;
    int tid = threadIdx.x;
    int d   = tid & 127;
    int ah  = (tid >> 7) * 8;

    int t0c = c * LC;
    int t1c = t0c + LC; if (t1c > TT) t1c = TT;
    int nb  = (t1c - t0c + 7) >> 3;
    int ntl = t1c - t0c;

    {
        int nvt0 = t1c - t0c; if (nvt0 > 8) nvt0 = 8;
        uint32_t ydst = smem_u32(Ys[0]);
        const float* ysrc = g_Y + t0c * 384;
        for (int i = tid; i < nvt0 * 96; i += 256)
            asm volatile("cp.async.ca.shared.global [%0], [%1], 16;"
                         :: "r"(ydst + i * 16), "l"(ysrc + i * 4));
        asm volatile("cp.async.commit_group;");
    }
    for (int i = tid; i < ntl * 64; i += 256) {
        int tl = i >> 6, r = i & 63, al = r >> 2, w = r & 3;
        Xt[(tl * 16 + al) * 4 + w] =
            (w < 3) ? in[(size_t)(2 * (t0c + tl) + w) * H + a0 + al] : 0.0f;
    }

    float z[8], lam[8];
#pragma unroll
    for (int k = 0; k < 8; k++) {
        lam[k] = Lam[(a0 + ah + k) * H + d];
        z[k]   = 0.0f;
    }

    for (int e = 0; e < nb; e++) {
        asm volatile("cp.async.wait_group 0;");
        __syncthreads();
        if (e + 1 < nb) {
            int tb1  = t0c + (e + 1) * 8;
            int nvt1 = t1c - tb1; if (nvt1 > 8) nvt1 = 8;
            uint32_t ydst = smem_u32(Ys[(e + 1) & 1]);
            const float* ysrc = g_Y + tb1 * 384;
            for (int i = tid; i < nvt1 * 96; i += 256)
                asm volatile("cp.async.ca.shared.global [%0], [%1], 16;"
                             :: "r"(ydst + i * 16), "l"(ysrc + i * 4));
            asm volatile("cp.async.commit_group;");
        }
        int tb  = t0c + e * 8;
        int nvt = t1c - tb; if (nvt > 8) nvt = 8;
        const float* Yb = Ys[e & 1];
        for (int tl = 0; tl < nvt; tl++) {
            float y0 = Yb[tl * 384 + d];
            float y1 = Yb[tl * 384 + 128 + d];
            float y2 = Yb[tl * 384 + 256 + d];
            int tli = tb - t0c + tl;
#pragma unroll
            for (int k = 0; k < 8; k++) {
                float4 xv = *(const float4*)&Xt[(tli * 16 + ah + k) * 4];
                float u = xv.x * y0 + xv.y * y1 + xv.z * y2;
                z[k] = fmaf(lam[k], z[k], u);
            }
        }
    }

#pragma unroll
    for (int k = 0; k < 8; k++) g_S[c * NELEM + (a0 + ah + k) * H + d] = z[k];
}

// ---------------------------------------------------------------------------
// Kernel 3: sequential carry combine across chunks (unroll 4).
// ---------------------------------------------------------------------------
__global__ void combine_kernel(const float* __restrict__ Lam) {
    int e = blockIdx.x * 256 + threadIdx.x;
    float lam = Lam[e];
    float p = lam;  // lam^32 via 5 squarings
    p = p * p; p = p * p; p = p * p; p = p * p; p = p * p;
    float cin = 0.0f;
    for (int c = 0; c < NC; c += 4) {
        float s0 = g_S[(c + 0) * NELEM + e];
        float s1 = g_S[(c + 1) * NELEM + e];
        float s2 = g_S[(c + 2) * NELEM + e];
        float s3 = g_S[(c + 3) * NELEM + e];
        g_cin[(c + 0) * NELEM + e] = cin; cin = fmaf(p, cin, s0);
        g_cin[(c + 1) * NELEM + e] = cin; cin = fmaf(p, cin, s1);
        g_cin[(c + 2) * NELEM + e] = cin; cin = fmaf(p, cin, s2);
        g_cin[(c + 3) * NELEM + e] = cin; cin = fmaf(p, cin, s3);
    }
}

// ---------------------------------------------------------------------------
// Kernel 4: FUSED scan + GEMM, 512-thread warp-specialized persistent CTAs.
//  8 producer warps: thread owns 2a x 4d (a = a0 + 2*wrp + j, d = 4*lane..).
//  8 consumer warps: 16 h-rows each (afr 32 regs) x full 128-ta panel;
//    ldmatrix.x4 B-frags, e/o parity mma, coalesced st.global.cs.v4.
//  <=64 regs/thread -> 2 CTAs/SM = 32 warps (2x R13 occupancy).
//  One barrier per epoch; Y(bi+1) (+ chunk-edge Xr) cp.async prefetched.
// ---------------------------------------------------------------------------
__global__ __launch_bounds__(512, 2) void fused_kernel(const float* __restrict__ in,
                                                       const float* __restrict__ Lam,
                                                       const float* __restrict__ Cm,
                                                       float* __restrict__ out) {
    extern __shared__ float smem[];
    __half* ZsA = (__half*)smem;                 // 128*ZSH halves
    __half* ZsB = ZsA + 128 * ZSH;
    float*  Ys0 = (float*)(ZsB + 128 * ZSH);     // 8*384 floats
    float*  Ys1 = Ys0 + 8 * 384;
    float*  Xr  = Ys1 + 8 * 384;                 // 2 * XRS floats

    int tid = threadIdx.x;
    int cy  = blockIdx.y;
    int a0  = blockIdx.x * 16;
    int wrp = tid >> 5, l = tid & 31;

    bool producer = (wrp < 8);
    int Tbase = cy * 128;

    // ---- producer state: 2a x 4d ----
    int pd4 = l * 4;
    float z[8], lam[8];
    int prow[2];
    if (producer) {
#pragma unroll
        for (int j = 0; j < 2; j++) {
            int arow = 2 * wrp + j;          // a_local 0..15
            int a = a0 + arow;
            float4 lv = *(const float4*)&Lam[a * H + pd4];
            lam[j * 4 + 0] = lv.x; lam[j * 4 + 1] = lv.y;
            lam[j * 4 + 2] = lv.z; lam[j * 4 + 3] = lv.w;
            prow[j] = ((arow >> 1) & 1) * 8 + 2 * (arow >> 2) + (arow & 1);
        }
        // prologue prefetch: Y(0) + Xr(chunk 0), one commit group (256 prod thr)
        int nvt0 = TT - Tbase; if (nvt0 > 8) nvt0 = 8;
        uint32_t ydst = smem_u32(Ys0);
        const float* ysrc = g_Y + (size_t)Tbase * 384;
        for (int i = tid; i < nvt0 * 96; i += 256)
            asm volatile("cp.async.ca.shared.global [%0], [%1], 16;"
                         :: "r"(ydst + i * 16), "l"(ysrc + i * 4));
        uint32_t xdst = smem_u32(Xr);
        for (int i = tid; i < 67 * 4; i += 256) {
            int r = i >> 2, q = i & 3;
            int row = 2 * Tbase + r;
            if (row < 8192)
                asm volatile("cp.async.ca.shared.global [%0], [%1], 16;"
                             :: "r"(xdst + (r * 16 + q * 4) * 4),
                                "l"(in + (size_t)row * H + a0 + q * 4));
        }
        asm volatile("cp.async.commit_group;");
    }

    // ---- consumer state: 16 h-rows each ----
    int grp = l >> 2, thr = l & 3;
    int cw  = wrp - 8;
    int h0  = cw * 16;
    uint32_t lmoff = (uint32_t)((l & 7) * ZSH * 2 + (l >> 3) * 16);
    uint32_t afr[8][4];
    if (!producer) {
#pragma unroll
        for (int kt = 0; kt < 8; kt++) {
            int cb = kt * 16 + 2 * thr;
            const float* r0 = Cm + (h0 + grp) * H;
            const float* r1 = Cm + (h0 + grp + 8) * H;
            __half2 p0 = __floats2half2_rn(r0[cb],     r0[cb + 1]);
            __half2 p1 = __floats2half2_rn(r1[cb],     r1[cb + 1]);
            __half2 p2 = __floats2half2_rn(r0[cb + 8], r0[cb + 9]);
            __half2 p3 = __floats2half2_rn(r1[cb + 8], r1[cb + 9]);
            afr[kt][0] = *(uint32_t*)&p0;
            afr[kt][1] = *(uint32_t*)&p1;
            afr[kt][2] = *(uint32_t*)&p2;
            afr[kt][3] = *(uint32_t*)&p3;
        }
    }

    const int NB = 4 * CPC;   // 16 batches per CTA

    for (int bi = 0; bi <= NB; bi++) {
        asm volatile("cp.async.wait_group 0;");
        __syncthreads();

        if (producer && bi < NB) {
            int tb = Tbase + bi * 8;

            // prefetch Y(bi+1) (+ next chunk's Xr at chunk edge)
            if (bi + 1 < NB) {
                int tb1  = tb + 8;
                int nvt1 = TT - tb1; if (nvt1 > 8) nvt1 = 8;
                uint32_t ydst = smem_u32(((bi + 1) & 1) ? Ys1 : Ys0);
                const float* ysrc = g_Y + (size_t)tb1 * 384;
                for (int i = tid; i < nvt1 * 96; i += 256)
                    asm volatile("cp.async.ca.shared.global [%0], [%1], 16;"
                                 :: "r"(ydst + i * 16), "l"(ysrc + i * 4));
                if ((bi & 3) == 3) {
                    int ck1  = (bi >> 2) + 1;
                    int t0c1 = Tbase + ck1 * 32;
                    uint32_t xdst = smem_u32(Xr + (ck1 & 1) * XRS);
                    for (int i = tid; i < 67 * 4; i += 256) {
                        int r = i >> 2, q = i & 3;
                        int row = 2 * t0c1 + r;
                        if (row < 8192)
                            asm volatile("cp.async.ca.shared.global [%0], [%1], 16;"
                                         :: "r"(xdst + (r * 16 + q * 4) * 4),
                                            "l"(in + (size_t)row * H + a0 + q * 4));
                    }
                }
                asm volatile("cp.async.commit_group;");
            }

            // chunk start: reload carry-in
            if ((bi & 3) == 0) {
                int gc = cy * CPC + (bi >> 2);
#pragma unroll
                for (int j = 0; j < 2; j++) {
                    int a = a0 + 2 * wrp + j;
                    float4 cv = *(const float4*)&g_cin[gc * NELEM + a * H + pd4];
                    z[j * 4 + 0] = cv.x; z[j * 4 + 1] = cv.y;
                    z[j * 4 + 2] = cv.z; z[j * 4 + 3] = cv.w;
                }
            }

            // ---- scan batch bi -> Zs[bi&1] (permuted rows) ----
            int nvt = TT - tb; if (nvt > 8) nvt = 8;
            const float* Yb = (bi & 1) ? Ys1 : Ys0;
            const float* Xb = Xr + ((bi >> 2) & 1) * XRS;
            __half* Zb = (bi & 1) ? ZsB : ZsA;
            int lb = (bi & 3) * 8;
            for (int tl = 0; tl < nvt; tl++) {
                float4 y0 = *(const float4*)&Yb[tl * 384 + pd4];
                float4 y1 = *(const float4*)&Yb[tl * 384 + 128 + pd4];
                float4 y2 = *(const float4*)&Yb[tl * 384 + 256 + pd4];
                int lr = 2 * (lb + tl);
#pragma unroll
                for (int j = 0; j < 2; j++) {
                    float xa = Xb[(lr + 0) * 16 + 2 * wrp + j];
                    float xm = Xb[(lr + 1) * 16 + 2 * wrp + j];
                    float xc = Xb[(lr + 2) * 16 + 2 * wrp + j];
                    float u0 = xa * y0.x + xm * y1.x + xc * y2.x;
                    float u1 = xa * y0.y + xm * y1.y + xc * y2.y;
                    float u2 = xa * y0.z + xm * y1.z + xc * y2.z;
                    float u3 = xa * y0.w + xm * y1.w + xc * y2.w;
                    z[j * 4 + 0] = fmaf(lam[j * 4 + 0], z[j * 4 + 0], u0);
                    z[j * 4 + 1] = fmaf(lam[j * 4 + 1], z[j * 4 + 1], u1);
                    z[j * 4 + 2] = fmaf(lam[j * 4 + 2], z[j * 4 + 2], u2);
                    z[j * 4 + 3] = fmaf(lam[j * 4 + 3], z[j * 4 + 3], u3);
                    __half2 p0 = __floats2half2_rn(z[j * 4 + 0], z[j * 4 + 1]);
                    __half2 p1 = __floats2half2_rn(z[j * 4 + 2], z[j * 4 + 3]);
                    uint2 pk;
                    pk.x = *(uint32_t*)&p0;
                    pk.y = *(uint32_t*)&p1;
                    *(uint2*)&Zb[(tl * 16 + prow[j]) * ZSH + pd4] = pk;
                }
            }
        } else if (!producer && bi > 0) {
            int tb = Tbase + (bi - 1) * 8;
            const __half* Zb = ((bi - 1) & 1) ? ZsB : ZsA;
            uint32_t zbase = smem_u32(Zb) + lmoff;
            for (int tl = 0; tl < 8; tl++) {
                int t = tb + tl;
                if (t >= TT) break;
                float ae[4], ao[4];
#pragma unroll
                for (int i = 0; i < 4; i++) { ae[i] = 0.0f; ao[i] = 0.0f; }
                uint32_t zr_e = zbase + (uint32_t)((tl * 16) * ZSH * 2);
                uint32_t zr_o = zbase + (uint32_t)((tl * 16 + 8) * ZSH * 2);
#pragma unroll
                for (int kp = 0; kp < 4; kp++) {
                    uint32_t be[4], bo[4];
                    asm volatile(
                        "ldmatrix.sync.aligned.m8n8.x4.shared.b16 "
                        "{%0,%1,%2,%3}, [%4];"
                        : "=r"(be[0]), "=r"(be[1]), "=r"(be[2]), "=r"(be[3])
                        : "r"(zr_e + (uint32_t)(kp * 64)));
                    asm volatile(
                        "ldmatrix.sync.aligned.m8n8.x4.shared.b16 "
                        "{%0,%1,%2,%3}, [%4];"
                        : "=r"(bo[0]), "=r"(bo[1]), "=r"(bo[2]), "=r"(bo[3])
                        : "r"(zr_o + (uint32_t)(kp * 64)));
                    int kt = kp * 2;
#pragma unroll
                    for (int q = 0; q < 2; q++) {
                        asm volatile(
                            "mma.sync.aligned.m16n8k16.row.col.f32.f16.f16.f32 "
                            "{%0,%1,%2,%3}, {%4,%5,%6,%7}, {%8,%9}, {%0,%1,%2,%3};"
                            : "+f"(ae[0]), "+f"(ae[1]), "+f"(ae[2]), "+f"(ae[3])
                            : "r"(afr[kt + q][0]), "r"(afr[kt + q][1]),
                              "r"(afr[kt + q][2]), "r"(afr[kt + q][3]),
                              "r"(be[q * 2]), "r"(be[q * 2 + 1]));
                        asm volatile(
                            "mma.sync.aligned.m16n8k16.row.col.f32.f16.f16.f32 "
                            "{%0,%1,%2,%3}, {%4,%5,%6,%7}, {%8,%9}, {%0,%1,%2,%3};"
                            : "+f"(ao[0]), "+f"(ao[1]), "+f"(ao[2]), "+f"(ao[3])
                            : "r"(afr[kt + q][0]), "r"(afr[kt + q][1]),
                              "r"(afr[kt + q][2]), "r"(afr[kt + q][3]),
                              "r"(bo[q * 2]), "r"(bo[q * 2 + 1]));
                    }
                }
                float* ob = out + (size_t)t * NELEM + a0 + 4 * thr;
                asm volatile("st.global.cs.v4.f32 [%0], {%1,%2,%3,%4};"
                             :: "l"(ob + (size_t)(h0 + grp) * H),
                                "f"(ae[0]), "f"(ae[1]), "f"(ao[0]), "f"(ao[1]));
                asm volatile("st.global.cs.v4.f32 [%0], {%1,%2,%3,%4};"
                             :: "l"(ob + (size_t)(h0 + grp + 8) * H),
                                "f"(ae[2]), "f"(ae[3]), "f"(ao[2]), "f"(ao[3]));
            }
        }
    }
}

// ---------------------------------------------------------------------------
// Launch: prep -> scan0 -> combine -> fused(512-thread persistent)
// Output layout: zs_out (T*H*H floats) followed by os (T*H floats).
// ---------------------------------------------------------------------------
extern "C" void kernel_launch(void* const* d_in, const int* in_sizes, int n_in,
                              void* d_out, int out_size) {
    const float* in  = (const float*)d_in[0];   // input_sequence (8192,128)
    const float* lam = (const float*)d_in[1];   // Lambda_bar (128,128)
    const float* Cm  = (const float*)d_in[2];   // C_tilde (128,128)
    const float* wq  = (const float*)d_in[3];   // w_q (3,3)
    const float* Dv  = (const float*)d_in[4];   // D (3,)
    (void)in_sizes; (void)n_in; (void)out_size;

    float* out    = (float*)d_out;
    float* os_out = out + (size_t)TT * NELEM;

    // smem: 2x Zs (halves) + 2x Ys + 2x Xr
    const int fused_smem = 2 * 128 * ZSH * (int)sizeof(__half)
                         + 2 * 8 * 384 * (int)sizeof(float)
                         + 2 * XRS * (int)sizeof(float);
    cudaFuncSetAttribute(fused_kernel, cudaFuncAttributeMaxDynamicSharedMemorySize,
                         fused_smem);

    prep_kernel<<<TT, H>>>(in, wq, Dv, os_out);
    scan0_kernel<<<dim3(8, NC), 256>>>(in, lam);
    combine_kernel<<<NELEM / 256, 256>>>(lam);
    fused_kernel<<<dim3(8, NC / CPC), 512, fused_smem>>>(in, lam, Cm, out);
}

// round 15
// speedup vs baseline: 1.4785x; 1.4785x over previous
#include <cuda_runtime.h>
#include <cuda_fp16.h>
#include <cstdint>

// Problem constants (fixed by the dataset)
#define H 128
#define TT 4095          // (8192-3)/2 + 1
#define NG 32            // scan groups (length 128)
#define GLC 128          // group length in t
#define NELEM (H * H)    // 16384 state elements
#define ZSH 136          // padded Zs row stride in halves (conflict-free)
#define XRS 1072         // Xr buffer floats (67 rows x 16)

// Scratch (allocation-free rule: __device__ globals)
static __device__ float g_Y[TT * 3 * H];   // Y[t][w][d] = (w_q @ X_t)[w,d]
static __device__ float g_S[NG * NELEM];   // group-local end states
static __device__ float g_cin[NG * NELEM]; // carry-in per group

static __device__ __forceinline__ uint32_t smem_u32(const void* p) {
    uint32_t a;
    asm("{ .reg .u64 t; cvta.to.shared.u64 t, %1; cvt.u32.u64 %0, t; }"
        : "=r"(a) : "l"(p));
    return a;
}

// ---------------------------------------------------------------------------
// Kernel 1: Y[t][w][:] = sum_v wq[w][v]*x[2t+v][:], os[t][:] = sum_w D[w]*x[2t+w][:]
// ---------------------------------------------------------------------------
__global__ void prep_kernel(const float* __restrict__ in,
                            const float* __restrict__ wq,
                            const float* __restrict__ Dv,
                            float* __restrict__ os_out) {
    int t = blockIdx.x;
    int d = threadIdx.x;
    float x0 = in[(2 * t + 0) * H + d];
    float x1 = in[(2 * t + 1) * H + d];
    float x2 = in[(2 * t + 2) * H + d];
    g_Y[(t * 3 + 0) * H + d] = wq[0] * x0 + wq[1] * x1 + wq[2] * x2;
    g_Y[(t * 3 + 1) * H + d] = wq[3] * x0 + wq[4] * x1 + wq[5] * x2;
    g_Y[(t * 3 + 2) * H + d] = wq[6] * x0 + wq[7] * x1 + wq[8] * x2;
    os_out[t * H + d] = Dv[0] * x0 + Dv[1] * x1 + Dv[2] * x2;
}

// ---------------------------------------------------------------------------
// Kernel 2: group-local scan (zero init), 128 t per group, grid (8, 32).
// Double-buffered Y prefetch; Xt triplet table staged once per group.
// ---------------------------------------------------------------------------
__global__ __launch_bounds__(256) void scan0_kernel(const float* __restrict__ in,
                                                    const float* __restrict__ Lam) {
    __shared__ float Ys[2][8 * 384];
    __shared__ float Xt[GLC * 16 * 4];   // [tl][a_local][w0..w2, pad]

    int g   = blockIdx.y;
    int a0  = blockIdx.x * 16;
    int tid = threadIdx.x;
    int d   = tid & 127;
    int ah  = (tid >> 7) * 8;

    int t0c = g * GLC;
    int t1c = t0c + GLC; if (t1c > TT) t1c = TT;
    int ntl = t1c - t0c;
    int nb  = (ntl + 7) >> 3;   // 16

    {
        int nvt0 = ntl; if (nvt0 > 8) nvt0 = 8;
        uint32_t ydst = smem_u32(Ys[0]);
        const float* ysrc = g_Y + (size_t)t0c * 384;
        for (int i = tid; i < nvt0 * 96; i += 256)
            asm volatile("cp.async.ca.shared.global [%0], [%1], 16;"
                         :: "r"(ydst + i * 16), "l"(ysrc + i * 4));
        asm volatile("cp.async.commit_group;");
    }
    for (int i = tid; i < ntl * 64; i += 256) {
        int tl = i >> 6, r = i & 63, al = r >> 2, w = r & 3;
        Xt[(tl * 16 + al) * 4 + w] =
            (w < 3) ? in[(size_t)(2 * (t0c + tl) + w) * H + a0 + al] : 0.0f;
    }

    float z[8], lam[8];
#pragma unroll
    for (int k = 0; k < 8; k++) {
        lam[k] = Lam[(a0 + ah + k) * H + d];
        z[k]   = 0.0f;
    }

    for (int e = 0; e < nb; e++) {
        asm volatile("cp.async.wait_group 0;");
        __syncthreads();
        if (e + 1 < nb) {
            int tb1  = t0c + (e + 1) * 8;
            int nvt1 = t1c - tb1; if (nvt1 > 8) nvt1 = 8;
            uint32_t ydst = smem_u32(Ys[(e + 1) & 1]);
            const float* ysrc = g_Y + (size_t)tb1 * 384;
            for (int i = tid; i < nvt1 * 96; i += 256)
                asm volatile("cp.async.ca.shared.global [%0], [%1], 16;"
                             :: "r"(ydst + i * 16), "l"(ysrc + i * 4));
            asm volatile("cp.async.commit_group;");
        }
        int tb  = t0c + e * 8;
        int nvt = t1c - tb; if (nvt > 8) nvt = 8;
        const float* Yb = Ys[e & 1];
        for (int tl = 0; tl < nvt; tl++) {
            float y0 = Yb[tl * 384 + d];
            float y1 = Yb[tl * 384 + 128 + d];
            float y2 = Yb[tl * 384 + 256 + d];
            int tli = tb - t0c + tl;
#pragma unroll
            for (int k = 0; k < 8; k++) {
                float4 xv = *(const float4*)&Xt[(tli * 16 + ah + k) * 4];
                float u = xv.x * y0 + xv.y * y1 + xv.z * y2;
                z[k] = fmaf(lam[k], z[k], u);
            }
        }
    }

#pragma unroll
    for (int k = 0; k < 8; k++) g_S[g * NELEM + (a0 + ah + k) * H + d] = z[k];
}

// ---------------------------------------------------------------------------
// Kernel 3: sequential carry combine across 32 groups (lam^128, unroll 4).
// ---------------------------------------------------------------------------
__global__ void combine_kernel(const float* __restrict__ Lam) {
    int e = blockIdx.x * 256 + threadIdx.x;
    float lam = Lam[e];
    float p = lam;  // lam^128 via 7 squarings
    p = p * p; p = p * p; p = p * p; p = p * p; p = p * p; p = p * p; p = p * p;
    float cin = 0.0f;
    for (int c = 0; c < NG; c += 4) {
        float s0 = g_S[(c + 0) * NELEM + e];
        float s1 = g_S[(c + 1) * NELEM + e];
        float s2 = g_S[(c + 2) * NELEM + e];
        float s3 = g_S[(c + 3) * NELEM + e];
        g_cin[(c + 0) * NELEM + e] = cin; cin = fmaf(p, cin, s0);
        g_cin[(c + 1) * NELEM + e] = cin; cin = fmaf(p, cin, s1);
        g_cin[(c + 2) * NELEM + e] = cin; cin = fmaf(p, cin, s2);
        g_cin[(c + 3) * NELEM + e] = cin; cin = fmaf(p, cin, s3);
    }
}

// ---------------------------------------------------------------------------
// Kernel 4: FUSED scan + GEMM, warp-specialized persistent CTAs (R13 proven).
//  Grid (8, 32): CTA owns a-tile and 128 consecutive t as ONE pipeline,
//  carry loaded once at bi==0 then continuous (exact prefix).
//  Producers (warps 0-3): 4a x 4d; Y(bi+1) + chunk Xr cp.async prefetched.
//  Consumers (warps 4-7): 32 h-rows x full panel; ldmatrix.x4, e/o mma,
//  coalesced st.global.cs.v4. ONE barrier per epoch.
// ---------------------------------------------------------------------------
__global__ __launch_bounds__(256, 2) void fused_kernel(const float* __restrict__ in,
                                                       const float* __restrict__ Lam,
                                                       const float* __restrict__ Cm,
                                                       float* __restrict__ out) {
    extern __shared__ float smem[];
    __half* ZsA = (__half*)smem;                 // 128*ZSH halves
    __half* ZsB = ZsA + 128 * ZSH;
    float*  Ys0 = (float*)(ZsB + 128 * ZSH);     // 8*384 floats
    float*  Ys1 = Ys0 + 8 * 384;
    float*  Xr  = Ys1 + 8 * 384;                 // 2 * XRS floats

    int tid = threadIdx.x;
    int cy  = blockIdx.y;
    int a0  = blockIdx.x * 16;
    int wrp = tid >> 5, l = tid & 31;

    bool producer = (wrp < 4);
    int Tbase = cy * GLC;

    // ---- producer state: 4a x 4d ----
    int pd4 = l * 4;
    int pag = wrp;
    float z[16], lam[16];
    int prow[4];
    if (producer) {
#pragma unroll
        for (int j = 0; j < 4; j++) {
            int a = a0 + pag * 4 + j;
            float4 lv = *(const float4*)&Lam[a * H + pd4];
            float4 cv = *(const float4*)&g_cin[cy * NELEM + a * H + pd4];
            lam[j * 4 + 0] = lv.x; lam[j * 4 + 1] = lv.y;
            lam[j * 4 + 2] = lv.z; lam[j * 4 + 3] = lv.w;
            z[j * 4 + 0] = cv.x; z[j * 4 + 1] = cv.y;
            z[j * 4 + 2] = cv.z; z[j * 4 + 3] = cv.w;
            prow[j] = ((j >> 1) & 1) * 8 + 2 * pag + (j & 1);
        }
        // prologue prefetch: Y(0) + Xr(first half), one commit group
        {
            int nvt0 = TT - Tbase; if (nvt0 > 8) nvt0 = 8;
            uint32_t ydst = smem_u32(Ys0);
            const float* ysrc = g_Y + (size_t)Tbase * 384;
            for (int i = tid; i < nvt0 * 96; i += 128)
                asm volatile("cp.async.ca.shared.global [%0], [%1], 16;"
                             :: "r"(ydst + i * 16), "l"(ysrc + i * 4));
            uint32_t xdst = smem_u32(Xr);
            for (int i = tid; i < 67 * 4; i += 128) {
                int r = i >> 2, q = i & 3;
                int row = 2 * Tbase + r;
                if (row < 8192)
                    asm volatile("cp.async.ca.shared.global [%0], [%1], 16;"
                                 :: "r"(xdst + (r * 16 + q * 4) * 4),
                                    "l"(in + (size_t)row * H + a0 + q * 4));
            }
            asm volatile("cp.async.commit_group;");
        }
    }

    // ---- consumer state: A fragments (C rows [h0,h0+32), fp16) ----
    int grp = l >> 2, thr = l & 3;
    int mg  = wrp - 4;
    int h0  = mg * 32;
    uint32_t lmoff = (uint32_t)((l & 7) * ZSH * 2 + (l >> 3) * 16);
    uint32_t afr[8][8];
    if (!producer) {
#pragma unroll
        for (int kt = 0; kt < 8; kt++) {
            int cb = kt * 16 + 2 * thr;
#pragma unroll
            for (int mt = 0; mt < 2; mt++) {
                const float* r0 = Cm + (h0 + mt * 16 + grp) * H;
                const float* r1 = Cm + (h0 + mt * 16 + grp + 8) * H;
                __half2 p0 = __floats2half2_rn(r0[cb],     r0[cb + 1]);
                __half2 p1 = __floats2half2_rn(r1[cb],     r1[cb + 1]);
                __half2 p2 = __floats2half2_rn(r0[cb + 8], r0[cb + 9]);
                __half2 p3 = __floats2half2_rn(r1[cb + 8], r1[cb + 9]);
                afr[kt][mt * 4 + 0] = *(uint32_t*)&p0;
                afr[kt][mt * 4 + 1] = *(uint32_t*)&p1;
                afr[kt][mt * 4 + 2] = *(uint32_t*)&p2;
                afr[kt][mt * 4 + 3] = *(uint32_t*)&p3;
            }
        }
    }

    const int NB = 16;   // 16 batches per CTA (128 t)

    for (int bi = 0; bi <= NB; bi++) {
        asm volatile("cp.async.wait_group 0;");
        __syncthreads();

        if (producer && bi < NB) {
            int tb = Tbase + bi * 8;

            // prefetch Y(bi+1) (+ second-half Xr at the midpoint)
            if (bi + 1 < NB) {
                int tb1  = tb + 8;
                int nvt1 = TT - tb1; if (nvt1 > 8) nvt1 = 8;
                uint32_t ydst = smem_u32(((bi + 1) & 1) ? Ys1 : Ys0);
                const float* ysrc = g_Y + (size_t)tb1 * 384;
                for (int i = tid; i < nvt1 * 96; i += 128)
                    asm volatile("cp.async.ca.shared.global [%0], [%1], 16;"
                                 :: "r"(ydst + i * 16), "l"(ysrc + i * 4));
                if ((bi & 3) == 3) {
                    int ck1  = (bi >> 2) + 1;
                    int t0c1 = Tbase + ck1 * 32;
                    uint32_t xdst = smem_u32(Xr + (ck1 & 1) * XRS);
                    for (int i = tid; i < 67 * 4; i += 128) {
                        int r = i >> 2, q = i & 3;
                        int row = 2 * t0c1 + r;
                        if (row < 8192)
                            asm volatile("cp.async.ca.shared.global [%0], [%1], 16;"
                                         :: "r"(xdst + (r * 16 + q * 4) * 4),
                                            "l"(in + (size_t)row * H + a0 + q * 4));
                    }
                }
                asm volatile("cp.async.commit_group;");
            }

            // ---- scan batch bi -> Zs[bi&1] (carry continuous) ----
            int nvt = TT - tb; if (nvt > 8) nvt = 8;
            const float* Yb = (bi & 1) ? Ys1 : Ys0;
            const float* Xb = Xr + ((bi >> 2) & 1) * XRS;
            __half* Zb = (bi & 1) ? ZsB : ZsA;
            int lb = (bi & 3) * 8;
            for (int tl = 0; tl < nvt; tl++) {
                float4 y0 = *(const float4*)&Yb[tl * 384 + pd4];
                float4 y1 = *(const float4*)&Yb[tl * 384 + 128 + pd4];
                float4 y2 = *(const float4*)&Yb[tl * 384 + 256 + pd4];
                int lr = 2 * (lb + tl);
                float4 x0 = *(const float4*)&Xb[(lr + 0) * 16 + pag * 4];
                float4 x1 = *(const float4*)&Xb[(lr + 1) * 16 + pag * 4];
                float4 x2 = *(const float4*)&Xb[(lr + 2) * 16 + pag * 4];
                float xw[4][3] = {{x0.x, x1.x, x2.x}, {x0.y, x1.y, x2.y},
                                  {x0.z, x1.z, x2.z}, {x0.w, x1.w, x2.w}};
#pragma unroll
                for (int j = 0; j < 4; j++) {
                    float xa = xw[j][0], xm = xw[j][1], xc = xw[j][2];
                    float u0 = xa * y0.x + xm * y1.x + xc * y2.x;
                    float u1 = xa * y0.y + xm * y1.y + xc * y2.y;
                    float u2 = xa * y0.z + xm * y1.z + xc * y2.z;
                    float u3 = xa * y0.w + xm * y1.w + xc * y2.w;
                    z[j * 4 + 0] = fmaf(lam[j * 4 + 0], z[j * 4 + 0], u0);
                    z[j * 4 + 1] = fmaf(lam[j * 4 + 1], z[j * 4 + 1], u1);
                    z[j * 4 + 2] = fmaf(lam[j * 4 + 2], z[j * 4 + 2], u2);
                    z[j * 4 + 3] = fmaf(lam[j * 4 + 3], z[j * 4 + 3], u3);
                    __half2 p0 = __floats2half2_rn(z[j * 4 + 0], z[j * 4 + 1]);
                    __half2 p1 = __floats2half2_rn(z[j * 4 + 2], z[j * 4 + 3]);
                    uint2 pk;
                    pk.x = *(uint32_t*)&p0;
                    pk.y = *(uint32_t*)&p1;
                    *(uint2*)&Zb[(tl * 16 + prow[j]) * ZSH + pd4] = pk;
                }
            }
        } else if (!producer && bi > 0) {
            int tb = Tbase + (bi - 1) * 8;
            const __half* Zb = ((bi - 1) & 1) ? ZsB : ZsA;
            uint32_t zbase = smem_u32(Zb) + lmoff;
            for (int tl = 0; tl < 8; tl++) {
                int t = tb + tl;
                if (t >= TT) break;
                float ae[8], ao[8];
#pragma unroll
                for (int i = 0; i < 8; i++) { ae[i] = 0.0f; ao[i] = 0.0f; }
                uint32_t zr_e = zbase + (uint32_t)((tl * 16) * ZSH * 2);
                uint32_t zr_o = zbase + (uint32_t)((tl * 16 + 8) * ZSH * 2);
#pragma unroll
                for (int kp = 0; kp < 4; kp++) {
                    uint32_t be[4], bo[4];
                    asm volatile(
                        "ldmatrix.sync.aligned.m8n8.x4.shared.b16 "
                        "{%0,%1,%2,%3}, [%4];"
                        : "=r"(be[0]), "=r"(be[1]), "=r"(be[2]), "=r"(be[3])
                        : "r"(zr_e + (uint32_t)(kp * 64)));
                    asm volatile(
                        "ldmatrix.sync.aligned.m8n8.x4.shared.b16 "
                        "{%0,%1,%2,%3}, [%4];"
                        : "=r"(bo[0]), "=r"(bo[1]), "=r"(bo[2]), "=r"(bo[3])
                        : "r"(zr_o + (uint32_t)(kp * 64)));
                    int kt = kp * 2;
#pragma unroll
                    for (int q = 0; q < 2; q++) {
                        asm volatile(
                            "mma.sync.aligned.m16n8k16.row.col.f32.f16.f16.f32 "
                            "{%0,%1,%2,%3}, {%4,%5,%6,%7}, {%8,%9}, {%0,%1,%2,%3};"
                            : "+f"(ae[0]), "+f"(ae[1]), "+f"(ae[2]), "+f"(ae[3])
                            : "r"(afr[kt + q][0]), "r"(afr[kt + q][1]),
                              "r"(afr[kt + q][2]), "r"(afr[kt + q][3]),
                              "r"(be[q * 2]), "r"(be[q * 2 + 1]));
                        asm volatile(
                            "mma.sync.aligned.m16n8k16.row.col.f32.f16.f16.f32 "
                            "{%0,%1,%2,%3}, {%4,%5,%6,%7}, {%8,%9}, {%0,%1,%2,%3};"
                            : "+f"(ae[4]), "+f"(ae[5]), "+f"(ae[6]), "+f"(ae[7])
                            : "r"(afr[kt + q][4]), "r"(afr[kt + q][5]),
                              "r"(afr[kt + q][6]), "r"(afr[kt + q][7]),
                              "r"(be[q * 2]), "r"(be[q * 2 + 1]));
                        asm volatile(
                            "mma.sync.aligned.m16n8k16.row.col.f32.f16.f16.f32 "
                            "{%0,%1,%2,%3}, {%4,%5,%6,%7}, {%8,%9}, {%0,%1,%2,%3};"
                            : "+f"(ao[0]), "+f"(ao[1]), "+f"(ao[2]), "+f"(ao[3])
                            : "r"(afr[kt + q][0]), "r"(afr[kt + q][1]),
                              "r"(afr[kt + q][2]), "r"(afr[kt + q][3]),
                              "r"(bo[q * 2]), "r"(bo[q * 2 + 1]));
                        asm volatile(
                            "mma.sync.aligned.m16n8k16.row.col.f32.f16.f16.f32 "
                            "{%0,%1,%2,%3}, {%4,%5,%6,%7}, {%8,%9}, {%0,%1,%2,%3};"
                            : "+f"(ao[4]), "+f"(ao[5]), "+f"(ao[6]), "+f"(ao[7])
                            : "r"(afr[kt + q][4]), "r"(afr[kt + q][5]),
                              "r"(afr[kt + q][6]), "r"(afr[kt + q][7]),
                              "r"(bo[q * 2]), "r"(bo[q * 2 + 1]));
                    }
                }
                float* ob = out + (size_t)t * NELEM + a0 + 4 * thr;
                asm volatile("st.global.cs.v4.f32 [%0], {%1,%2,%3,%4};"
                             :: "l"(ob + (size_t)(h0 + grp) * H),
                                "f"(ae[0]), "f"(ae[1]), "f"(ao[0]), "f"(ao[1]));
                asm volatile("st.global.cs.v4.f32 [%0], {%1,%2,%3,%4};"
                             :: "l"(ob + (size_t)(h0 + grp + 8) * H),
                                "f"(ae[2]), "f"(ae[3]), "f"(ao[2]), "f"(ao[3]));
                asm volatile("st.global.cs.v4.f32 [%0], {%1,%2,%3,%4};"
                             :: "l"(ob + (size_t)(h0 + 16 + grp) * H),
                                "f"(ae[4]), "f"(ae[5]), "f"(ao[4]), "f"(ao[5]));
                asm volatile("st.global.cs.v4.f32 [%0], {%1,%2,%3,%4};"
                             :: "l"(ob + (size_t)(h0 + 24 + grp) * H),
                                "f"(ae[6]), "f"(ae[7]), "f"(ao[6]), "f"(ao[7]));
            }
        }
    }
}

// ---------------------------------------------------------------------------
// Launch: prep -> scan0 -> combine -> fused(persistent warp-specialized)
// Output layout: zs_out (T*H*H floats) followed by os (T*H floats).
// ---------------------------------------------------------------------------
extern "C" void kernel_launch(void* const* d_in, const int* in_sizes, int n_in,
                              void* d_out, int out_size) {
    const float* in  = (const float*)d_in[0];   // input_sequence (8192,128)
    const float* lam = (const float*)d_in[1];   // Lambda_bar (128,128)
    const float* Cm  = (const float*)d_in[2];   // C_tilde (128,128)
    const float* wq  = (const float*)d_in[3];   // w_q (3,3)
    const float* Dv  = (const float*)d_in[4];   // D (3,)
    (void)in_sizes; (void)n_in; (void)out_size;

    float* out    = (float*)d_out;
    float* os_out = out + (size_t)TT * NELEM;

    // fused smem: 2x Zs (halves) + 2x Ys + 2x Xr
    const int fused_smem = 2 * 128 * ZSH * (int)sizeof(__half)
                         + 2 * 8 * 384 * (int)sizeof(float)
                         + 2 * XRS * (int)sizeof(float);
    cudaFuncSetAttribute(fused_kernel, cudaFuncAttributeMaxDynamicSharedMemorySize,
                         fused_smem);

    prep_kernel<<<TT, H>>>(in, wq, Dv, os_out);
    scan0_kernel<<<dim3(8, NG), 256>>>(in, lam);
    combine_kernel<<<NELEM / 256, 256>>>(lam);
    fused_kernel<<<dim3(8, NG), 256, fused_smem>>>(in, lam, Cm, out);
}

// round 16
// speedup vs baseline: 1.5900x; 1.0754x over previous
#include <cuda_runtime.h>
#include <cuda_fp16.h>
#include <cstdint>

// Problem constants (fixed by the dataset)
#define H 128
#define TT 4095          // (8192-3)/2 + 1
#define NC 128           // scan chunks
#define LC 32            // chunk length (last chunk = 31)
#define NELEM (H * H)    // 16384 state elements
#define ZSH 136          // padded Zs row stride in halves (conflict-free)
#define XRS 1072         // Xr buffer floats (67 rows x 16)
#define NY 37            // fused grid.y: 296 CTAs = 2 per SM exactly

// Scratch (allocation-free rule: __device__ globals)
static __device__ float g_Y[TT * 3 * H];   // Y[t][w][d] = (w_q @ X_t)[w,d]
static __device__ float g_S[NC * NELEM];   // chunk-local end states
static __device__ float g_cin[NC * NELEM]; // carry-in per chunk

static __device__ __forceinline__ uint32_t smem_u32(const void* p) {
    uint32_t a;
    asm("{ .reg .u64 t; cvta.to.shared.u64 t, %1; cvt.u32.u64 %0, t; }"
        : "=r"(a) : "l"(p));
    return a;
}

// chunk partition for fused: y=0..16 -> 4 chunks, y=17..36 -> 3 chunks
static __device__ __forceinline__ int part_start(int y) {
    return (y <= 17) ? 4 * y : 68 + 3 * (y - 17);
}

// ---------------------------------------------------------------------------
// Kernel 1: Y[t][w][:] = sum_v wq[w][v]*x[2t+v][:], os[t][:] = sum_w D[w]*x[2t+w][:]
// ---------------------------------------------------------------------------
__global__ void prep_kernel(const float* __restrict__ in,
                            const float* __restrict__ wq,
                            const float* __restrict__ Dv,
                            float* __restrict__ os_out) {
    int t = blockIdx.x;
    int d = threadIdx.x;
    float x0 = in[(2 * t + 0) * H + d];
    float x1 = in[(2 * t + 1) * H + d];
    float x2 = in[(2 * t + 2) * H + d];
    g_Y[(t * 3 + 0) * H + d] = wq[0] * x0 + wq[1] * x1 + wq[2] * x2;
    g_Y[(t * 3 + 1) * H + d] = wq[3] * x0 + wq[4] * x1 + wq[5] * x2;
    g_Y[(t * 3 + 2) * H + d] = wq[6] * x0 + wq[7] * x1 + wq[8] * x2;
    os_out[t * H + d] = Dv[0] * x0 + Dv[1] * x1 + Dv[2] * x2;
}

// ---------------------------------------------------------------------------
// Kernel 2: chunk-local scan (zero init), double-buffered Y prefetch,
// Xt triplet layout.   [R13 proven]
// ---------------------------------------------------------------------------
__global__ __launch_bounds__(256) void scan0_kernel(const float* __restrict__ in,
                                                    const float* __restrict__ Lam) {
    __shared__ float Ys[2][8 * 384];
    __shared__ float Xt[LC * 16 * 4];

    int c   = blockIdx.y;
    int a0  = blockIdx.x * 16;
    int tid = threadIdx.x;
    int d   = tid & 127;
    int ah  = (tid >> 7) * 8;

    int t0c = c * LC;
    int t1c = t0c + LC; if (t1c > TT) t1c = TT;
    int nb  = (t1c - t0c + 7) >> 3;
    int ntl = t1c - t0c;

    {
        int nvt0 = t1c - t0c; if (nvt0 > 8) nvt0 = 8;
        uint32_t ydst = smem_u32(Ys[0]);
        const float* ysrc = g_Y + (size_t)t0c * 384;
        for (int i = tid; i < nvt0 * 96; i += 256)
            asm volatile("cp.async.ca.shared.global [%0], [%1], 16;"
                         :: "r"(ydst + i * 16), "l"(ysrc + i * 4));
        asm volatile("cp.async.commit_group;");
    }
    for (int i = tid; i < ntl * 64; i += 256) {
        int tl = i >> 6, r = i & 63, al = r >> 2, w = r & 3;
        Xt[(tl * 16 + al) * 4 + w] =
            (w < 3) ? in[(size_t)(2 * (t0c + tl) + w) * H + a0 + al] : 0.0f;
    }

    float z[8], lam[8];
#pragma unroll
    for (int k = 0; k < 8; k++) {
        lam[k] = Lam[(a0 + ah + k) * H + d];
        z[k]   = 0.0f;
    }

    for (int e = 0; e < nb; e++) {
        asm volatile("cp.async.wait_group 0;");
        __syncthreads();
        if (e + 1 < nb) {
            int tb1  = t0c + (e + 1) * 8;
            int nvt1 = t1c - tb1; if (nvt1 > 8) nvt1 = 8;
            uint32_t ydst = smem_u32(Ys[(e + 1) & 1]);
            const float* ysrc = g_Y + (size_t)tb1 * 384;
            for (int i = tid; i < nvt1 * 96; i += 256)
                asm volatile("cp.async.ca.shared.global [%0], [%1], 16;"
                             :: "r"(ydst + i * 16), "l"(ysrc + i * 4));
            asm volatile("cp.async.commit_group;");
        }
        int tb  = t0c + e * 8;
        int nvt = t1c - tb; if (nvt > 8) nvt = 8;
        const float* Yb = Ys[e & 1];
        for (int tl = 0; tl < nvt; tl++) {
            float y0 = Yb[tl * 384 + d];
            float y1 = Yb[tl * 384 + 128 + d];
            float y2 = Yb[tl * 384 + 256 + d];
            int tli = tb - t0c + tl;
#pragma unroll
            for (int k = 0; k < 8; k++) {
                float4 xv = *(const float4*)&Xt[(tli * 16 + ah + k) * 4];
                float u = xv.x * y0 + xv.y * y1 + xv.z * y2;
                z[k] = fmaf(lam[k], z[k], u);
            }
        }
    }

#pragma unroll
    for (int k = 0; k < 8; k++) g_S[c * NELEM + (a0 + ah + k) * H + d] = z[k];
}

// ---------------------------------------------------------------------------
// Kernel 3: sequential carry combine across chunks (unroll 4).
// ---------------------------------------------------------------------------
__global__ void combine_kernel(const float* __restrict__ Lam) {
    int e = blockIdx.x * 256 + threadIdx.x;
    float lam = Lam[e];
    float p = lam;  // lam^32 via 5 squarings
    p = p * p; p = p * p; p = p * p; p = p * p; p = p * p;
    float cin = 0.0f;
    for (int c = 0; c < NC; c += 4) {
        float s0 = g_S[(c + 0) * NELEM + e];
        float s1 = g_S[(c + 1) * NELEM + e];
        float s2 = g_S[(c + 2) * NELEM + e];
        float s3 = g_S[(c + 3) * NELEM + e];
        g_cin[(c + 0) * NELEM + e] = cin; cin = fmaf(p, cin, s0);
        g_cin[(c + 1) * NELEM + e] = cin; cin = fmaf(p, cin, s1);
        g_cin[(c + 2) * NELEM + e] = cin; cin = fmaf(p, cin, s2);
        g_cin[(c + 3) * NELEM + e] = cin; cin = fmaf(p, cin, s3);
    }
}

// ---------------------------------------------------------------------------
// Kernel 4: FUSED scan + GEMM, warp-specialized persistent CTAs (R13 body),
// BALANCED grid (8, 37) = 296 CTAs = exactly 2 per SM.
//  CTA (ax, cy) processes chunks [part_start(cy), part_start(cy+1)) — 4 chunks
//  for cy<=16, 3 for cy>=17. Co-resident pairs (cy, cy+18/19) never both have
//  4 chunks -> per-SM load <= 7 chunk-units (vs 8 before).
//  Per-chunk carry reload from g_cin (any partition legal).
// ---------------------------------------------------------------------------
__global__ __launch_bounds__(256, 2) void fused_kernel(const float* __restrict__ in,
                                                       const float* __restrict__ Lam,
                                                       const float* __restrict__ Cm,
                                                       float* __restrict__ out) {
    extern __shared__ float smem[];
    __half* ZsA = (__half*)smem;                 // 128*ZSH halves
    __half* ZsB = ZsA + 128 * ZSH;
    float*  Ys0 = (float*)(ZsB + 128 * ZSH);     // 8*384 floats
    float*  Ys1 = Ys0 + 8 * 384;
    float*  Xr  = Ys1 + 8 * 384;                 // 2 * XRS floats

    int tid = threadIdx.x;
    int cy  = blockIdx.y;
    int a0  = blockIdx.x * 16;
    int wrp = tid >> 5, l = tid & 31;

    bool producer = (wrp < 4);
    int s_ck  = part_start(cy);
    int e_ck  = part_start(cy + 1);
    int NB    = (e_ck - s_ck) * 4;               // 12 or 16 epochs
    int Tbase = s_ck * 32;

    // ---- producer state ----
    int pd4 = l * 4;
    int pag = wrp;
    float z[16], lam[16];
    int prow[4];
    if (producer) {
#pragma unroll
        for (int j = 0; j < 4; j++) {
            int a = a0 + pag * 4 + j;
            float4 lv = *(const float4*)&Lam[a * H + pd4];
            lam[j * 4 + 0] = lv.x; lam[j * 4 + 1] = lv.y;
            lam[j * 4 + 2] = lv.z; lam[j * 4 + 3] = lv.w;
            prow[j] = ((j >> 1) & 1) * 8 + 2 * pag + (j & 1);
        }
        // prologue prefetch: Y(0) + Xr(first chunk), one commit group
        {
            int nvt0 = TT - Tbase; if (nvt0 > 8) nvt0 = 8;
            uint32_t ydst = smem_u32(Ys0);
            const float* ysrc = g_Y + (size_t)Tbase * 384;
            for (int i = tid; i < nvt0 * 96; i += 128)
                asm volatile("cp.async.ca.shared.global [%0], [%1], 16;"
                             :: "r"(ydst + i * 16), "l"(ysrc + i * 4));
            uint32_t xdst = smem_u32(Xr);
            for (int i = tid; i < 67 * 4; i += 128) {
                int r = i >> 2, q = i & 3;
                int row = 2 * Tbase + r;
                if (row < 8192)
                    asm volatile("cp.async.ca.shared.global [%0], [%1], 16;"
                                 :: "r"(xdst + (r * 16 + q * 4) * 4),
                                    "l"(in + (size_t)row * H + a0 + q * 4));
            }
            asm volatile("cp.async.commit_group;");
        }
    }

    // ---- consumer state: A fragments (C rows [h0,h0+32), fp16) ----
    int grp = l >> 2, thr = l & 3;
    int mg  = wrp - 4;
    int h0  = mg * 32;
    uint32_t lmoff = (uint32_t)((l & 7) * ZSH * 2 + (l >> 3) * 16);
    uint32_t afr[8][8];
    if (!producer) {
#pragma unroll
        for (int kt = 0; kt < 8; kt++) {
            int cb = kt * 16 + 2 * thr;
#pragma unroll
            for (int mt = 0; mt < 2; mt++) {
                const float* r0 = Cm + (h0 + mt * 16 + grp) * H;
                const float* r1 = Cm + (h0 + mt * 16 + grp + 8) * H;
                __half2 p0 = __floats2half2_rn(r0[cb],     r0[cb + 1]);
                __half2 p1 = __floats2half2_rn(r1[cb],     r1[cb + 1]);
                __half2 p2 = __floats2half2_rn(r0[cb + 8], r0[cb + 9]);
                __half2 p3 = __floats2half2_rn(r1[cb + 8], r1[cb + 9]);
                afr[kt][mt * 4 + 0] = *(uint32_t*)&p0;
                afr[kt][mt * 4 + 1] = *(uint32_t*)&p1;
                afr[kt][mt * 4 + 2] = *(uint32_t*)&p2;
                afr[kt][mt * 4 + 3] = *(uint32_t*)&p3;
            }
        }
    }

    for (int bi = 0; bi <= NB; bi++) {
        asm volatile("cp.async.wait_group 0;");
        __syncthreads();

        if (producer && bi < NB) {
            int tb = Tbase + bi * 8;

            // prefetch Y(bi+1) (+ next chunk's Xr at chunk edge)
            if (bi + 1 < NB) {
                int tb1  = tb + 8;
                int nvt1 = TT - tb1; if (nvt1 > 8) nvt1 = 8;
                uint32_t ydst = smem_u32(((bi + 1) & 1) ? Ys1 : Ys0);
                const float* ysrc = g_Y + (size_t)tb1 * 384;
                for (int i = tid; i < nvt1 * 96; i += 128)
                    asm volatile("cp.async.ca.shared.global [%0], [%1], 16;"
                                 :: "r"(ydst + i * 16), "l"(ysrc + i * 4));
                if ((bi & 3) == 3) {
                    int ck1  = (bi >> 2) + 1;                  // local chunk index
                    int t0c1 = Tbase + ck1 * 32;
                    uint32_t xdst = smem_u32(Xr + (ck1 & 1) * XRS);
                    for (int i = tid; i < 67 * 4; i += 128) {
                        int r = i >> 2, q = i & 3;
                        int row = 2 * t0c1 + r;
                        if (row < 8192)
                            asm volatile("cp.async.ca.shared.global [%0], [%1], 16;"
                                         :: "r"(xdst + (r * 16 + q * 4) * 4),
                                            "l"(in + (size_t)row * H + a0 + q * 4));
                    }
                }
                asm volatile("cp.async.commit_group;");
            }

            // chunk start: reload carry-in (global chunk s_ck + local)
            if ((bi & 3) == 0) {
                int gc = s_ck + (bi >> 2);
#pragma unroll
                for (int j = 0; j < 4; j++) {
                    int a = a0 + pag * 4 + j;
                    float4 cv = *(const float4*)&g_cin[gc * NELEM + a * H + pd4];
                    z[j * 4 + 0] = cv.x; z[j * 4 + 1] = cv.y;
                    z[j * 4 + 2] = cv.z; z[j * 4 + 3] = cv.w;
                }
            }

            // ---- scan batch bi -> Zs[bi&1] ----
            int nvt = TT - tb; if (nvt > 8) nvt = 8;
            const float* Yb = (bi & 1) ? Ys1 : Ys0;
            const float* Xb = Xr + ((bi >> 2) & 1) * XRS;
            __half* Zb = (bi & 1) ? ZsB : ZsA;
            int lb = (bi & 3) * 8;
            for (int tl = 0; tl < nvt; tl++) {
                float4 y0 = *(const float4*)&Yb[tl * 384 + pd4];
                float4 y1 = *(const float4*)&Yb[tl * 384 + 128 + pd4];
                float4 y2 = *(const float4*)&Yb[tl * 384 + 256 + pd4];
                int lr = 2 * (lb + tl);
                float4 x0 = *(const float4*)&Xb[(lr + 0) * 16 + pag * 4];
                float4 x1 = *(const float4*)&Xb[(lr + 1) * 16 + pag * 4];
                float4 x2 = *(const float4*)&Xb[(lr + 2) * 16 + pag * 4];
                float xw[4][3] = {{x0.x, x1.x, x2.x}, {x0.y, x1.y, x2.y},
                                  {x0.z, x1.z, x2.z}, {x0.w, x1.w, x2.w}};
#pragma unroll
                for (int j = 0; j < 4; j++) {
                    float xa = xw[j][0], xm = xw[j][1], xc = xw[j][2];
                    float u0 = xa * y0.x + xm * y1.x + xc * y2.x;
                    float u1 = xa * y0.y + xm * y1.y + xc * y2.y;
                    float u2 = xa * y0.z + xm * y1.z + xc * y2.z;
                    float u3 = xa * y0.w + xm * y1.w + xc * y2.w;
                    z[j * 4 + 0] = fmaf(lam[j * 4 + 0], z[j * 4 + 0], u0);
                    z[j * 4 + 1] = fmaf(lam[j * 4 + 1], z[j * 4 + 1], u1);
                    z[j * 4 + 2] = fmaf(lam[j * 4 + 2], z[j * 4 + 2], u2);
                    z[j * 4 + 3] = fmaf(lam[j * 4 + 3], z[j * 4 + 3], u3);
                    __half2 p0 = __floats2half2_rn(z[j * 4 + 0], z[j * 4 + 1]);
                    __half2 p1 = __floats2half2_rn(z[j * 4 + 2], z[j * 4 + 3]);
                    uint2 pk;
                    pk.x = *(uint32_t*)&p0;
                    pk.y = *(uint32_t*)&p1;
                    *(uint2*)&Zb[(tl * 16 + prow[j]) * ZSH + pd4] = pk;
                }
            }
        } else if (!producer && bi > 0) {
            int tb = Tbase + (bi - 1) * 8;
            const __half* Zb = ((bi - 1) & 1) ? ZsB : ZsA;
            uint32_t zbase = smem_u32(Zb) + lmoff;
            for (int tl = 0; tl < 8; tl++) {
                int t = tb + tl;
                if (t >= TT) break;
                float ae[8], ao[8];
#pragma unroll
                for (int i = 0; i < 8; i++) { ae[i] = 0.0f; ao[i] = 0.0f; }
                uint32_t zr_e = zbase + (uint32_t)((tl * 16) * ZSH * 2);
                uint32_t zr_o = zbase + (uint32_t)((tl * 16 + 8) * ZSH * 2);
#pragma unroll
                for (int kp = 0; kp < 4; kp++) {
                    uint32_t be[4], bo[4];
                    asm volatile(
                        "ldmatrix.sync.aligned.m8n8.x4.shared.b16 "
                        "{%0,%1,%2,%3}, [%4];"
                        : "=r"(be[0]), "=r"(be[1]), "=r"(be[2]), "=r"(be[3])
                        : "r"(zr_e + (uint32_t)(kp * 64)));
                    asm volatile(
                        "ldmatrix.sync.aligned.m8n8.x4.shared.b16 "
                        "{%0,%1,%2,%3}, [%4];"
                        : "=r"(bo[0]), "=r"(bo[1]), "=r"(bo[2]), "=r"(bo[3])
                        : "r"(zr_o + (uint32_t)(kp * 64)));
                    int kt = kp * 2;
#pragma unroll
                    for (int q = 0; q < 2; q++) {
                        asm volatile(
                            "mma.sync.aligned.m16n8k16.row.col.f32.f16.f16.f32 "
                            "{%0,%1,%2,%3}, {%4,%5,%6,%7}, {%8,%9}, {%0,%1,%2,%3};"
                            : "+f"(ae[0]), "+f"(ae[1]), "+f"(ae[2]), "+f"(ae[3])
                            : "r"(afr[kt + q][0]), "r"(afr[kt + q][1]),
                              "r"(afr[kt + q][2]), "r"(afr[kt + q][3]),
                              "r"(be[q * 2]), "r"(be[q * 2 + 1]));
                        asm volatile(
                            "mma.sync.aligned.m16n8k16.row.col.f32.f16.f16.f32 "
                            "{%0,%1,%2,%3}, {%4,%5,%6,%7}, {%8,%9}, {%0,%1,%2,%3};"
                            : "+f"(ae[4]), "+f"(ae[5]), "+f"(ae[6]), "+f"(ae[7])
                            : "r"(afr[kt + q][4]), "r"(afr[kt + q][5]),
                              "r"(afr[kt + q][6]), "r"(afr[kt + q][7]),
                              "r"(be[q * 2]), "r"(be[q * 2 + 1]));
                        asm volatile(
                            "mma.sync.aligned.m16n8k16.row.col.f32.f16.f16.f32 "
                            "{%0,%1,%2,%3}, {%4,%5,%6,%7}, {%8,%9}, {%0,%1,%2,%3};"
                            : "+f"(ao[0]), "+f"(ao[1]), "+f"(ao[2]), "+f"(ao[3])
                            : "r"(afr[kt + q][0]), "r"(afr[kt + q][1]),
                              "r"(afr[kt + q][2]), "r"(afr[kt + q][3]),
                              "r"(bo[q * 2]), "r"(bo[q * 2 + 1]));
                        asm volatile(
                            "mma.sync.aligned.m16n8k16.row.col.f32.f16.f16.f32 "
                            "{%0,%1,%2,%3}, {%4,%5,%6,%7}, {%8,%9}, {%0,%1,%2,%3};"
                            : "+f"(ao[4]), "+f"(ao[5]), "+f"(ao[6]), "+f"(ao[7])
                            : "r"(afr[kt + q][4]), "r"(afr[kt + q][5]),
                              "r"(afr[kt + q][6]), "r"(afr[kt + q][7]),
                              "r"(bo[q * 2]), "r"(bo[q * 2 + 1]));
                    }
                }
                float* ob = out + (size_t)t * NELEM + a0 + 4 * thr;
                asm volatile("st.global.cs.v4.f32 [%0], {%1,%2,%3,%4};"
                             :: "l"(ob + (size_t)(h0 + grp) * H),
                                "f"(ae[0]), "f"(ae[1]), "f"(ao[0]), "f"(ao[1]));
                asm volatile("st.global.cs.v4.f32 [%0], {%1,%2,%3,%4};"
                             :: "l"(ob + (size_t)(h0 + grp + 8) * H),
                                "f"(ae[2]), "f"(ae[3]), "f"(ao[2]), "f"(ao[3]));
                asm volatile("st.global.cs.v4.f32 [%0], {%1,%2,%3,%4};"
                             :: "l"(ob + (size_t)(h0 + 16 + grp) * H),
                                "f"(ae[4]), "f"(ae[5]), "f"(ao[4]), "f"(ao[5]));
                asm volatile("st.global.cs.v4.f32 [%0], {%1,%2,%3,%4};"
                             :: "l"(ob + (size_t)(h0 + 24 + grp) * H),
                                "f"(ae[6]), "f"(ae[7]), "f"(ao[6]), "f"(ao[7]));
            }
        }
        __syncthreads();
    }
}

// ---------------------------------------------------------------------------
// Launch: prep -> scan0 -> combine -> fused(balanced persistent)
// Output layout: zs_out (T*H*H floats) followed by os (T*H floats).
// ---------------------------------------------------------------------------
extern "C" void kernel_launch(void* const* d_in, const int* in_sizes, int n_in,
                              void* d_out, int out_size) {
    const float* in  = (const float*)d_in[0];   // input_sequence (8192,128)
    const float* lam = (const float*)d_in[1];   // Lambda_bar (128,128)
    const float* Cm  = (const float*)d_in[2];   // C_tilde (128,128)
    const float* wq  = (const float*)d_in[3];   // w_q (3,3)
    const float* Dv  = (const float*)d_in[4];   // D (3,)
    (void)in_sizes; (void)n_in; (void)out_size;

    float* out    = (float*)d_out;
    float* os_out = out + (size_t)TT * NELEM;

    // smem: 2x Zs (halves) + 2x Ys + 2x Xr
    const int fused_smem = 2 * 128 * ZSH * (int)sizeof(__half)
                         + 2 * 8 * 384 * (int)sizeof(float)
                         + 2 * XRS * (int)sizeof(float);
    cudaFuncSetAttribute(fused_kernel, cudaFuncAttributeMaxDynamicSharedMemorySize,
                         fused_smem);

    prep_kernel<<<TT, H>>>(in, wq, Dv, os_out);
    scan0_kernel<<<dim3(8, NC), 256>>>(in, lam);
    combine_kernel<<<NELEM / 256, 256>>>(lam);
    fused_kernel<<<dim3(8, NY), 256, fused_smem>>>(in, lam, Cm, out);
}